// round 13
// baseline (speedup 1.0000x reference)
#include <cuda_runtime.h>
#include <cuda_fp16.h>
#include <cstdint>

// Problem constants
#define BB   16
#define SS   577
#define DD   1408
#define HH   16
#define HD   88
#define SCALE_F 0.10660035817780521f  // 1/sqrt(88)

#define MM   (BB * SS)      // 9232
#define N1   (3 * DD)       // 4224
#define KK   DD             // 1408

// ---------------------------------------------------------------------------
// Device-global scratch (all plain fp16)
// ---------------------------------------------------------------------------
__device__ __half g_hs[(size_t)MM * KK];
__device__ __half g_qkv[(size_t)MM * N1];
__device__ __half g_att[(size_t)MM * KK];
__device__ __half g_wqkv[(size_t)N1 * KK];      // transposed [N,K]
__device__ __half g_wproj[(size_t)DD * KK];     // transposed [N,K]

// ---------------------------------------------------------------------------
// PTX helpers (sm_80+ only; harness targets sm_103 w/o 'a' — no tcgen05)
// ---------------------------------------------------------------------------
__device__ __forceinline__ uint32_t smem_to_u32(const void* p) {
    uint32_t a;
    asm("{ .reg .u64 t; cvta.to.shared.u64 t, %1; cvt.u32.u64 %0, t; }"
        : "=r"(a) : "l"(p));
    return a;
}
__device__ __forceinline__ void cp16(uint32_t dst, const void* src, uint32_t sz) {
    asm volatile("cp.async.ca.shared.global [%0], [%1], 16, %2;"
                 :: "r"(dst), "l"(src), "r"(sz) : "memory");
}
#define CP_COMMIT() asm volatile("cp.async.commit_group;" ::: "memory")
#define CP_WAIT(n)  asm volatile("cp.async.wait_group %0;" :: "n"(n) : "memory")

__device__ __forceinline__ void ldsm_x4(uint32_t* r, uint32_t addr) {
    asm volatile("ldmatrix.sync.aligned.m8n8.x4.shared.b16 {%0,%1,%2,%3}, [%4];"
                 : "=r"(r[0]), "=r"(r[1]), "=r"(r[2]), "=r"(r[3]) : "r"(addr));
}
__device__ __forceinline__ void ldsm_x2(uint32_t* r, uint32_t addr) {
    asm volatile("ldmatrix.sync.aligned.m8n8.x2.shared.b16 {%0,%1}, [%2];"
                 : "=r"(r[0]), "=r"(r[1]) : "r"(addr));
}
__device__ __forceinline__ void ldsm_x2t(uint32_t* r, uint32_t addr) {
    asm volatile("ldmatrix.sync.aligned.m8n8.x2.trans.shared.b16 {%0,%1}, [%2];"
                 : "=r"(r[0]), "=r"(r[1]) : "r"(addr));
}
__device__ __forceinline__ void mma_f32(float* d, const uint32_t* a, const uint32_t* b) {
    asm volatile("mma.sync.aligned.m16n8k16.row.col.f32.f16.f16.f32 "
                 "{%0,%1,%2,%3}, {%4,%5,%6,%7}, {%8,%9}, {%0,%1,%2,%3};"
                 : "+f"(d[0]), "+f"(d[1]), "+f"(d[2]), "+f"(d[3])
                 : "r"(a[0]), "r"(a[1]), "r"(a[2]), "r"(a[3]), "r"(b[0]), "r"(b[1]));
}
__device__ __forceinline__ uint32_t pack_h2(float a, float b) {
    __half2 h = __floats2half2_rn(a, b);
    return *reinterpret_cast<uint32_t*>(&h);
}

// ---------------------------------------------------------------------------
// Round fp32 -> fp16, same layout.
// ---------------------------------------------------------------------------
__global__ void round_kernel(const float4* __restrict__ in,
                             uint2* __restrict__ out, int n4)
{
    int i = blockIdx.x * blockDim.x + threadIdx.x;
    if (i >= n4) return;
    float4 v = in[i];
    uint2 o;
    o.x = pack_h2(v.x, v.y);
    o.y = pack_h2(v.z, v.w);
    out[i] = o;
}

// ---------------------------------------------------------------------------
// Transpose + round: in fp32 [R, C] -> fp16 [C, R]
// ---------------------------------------------------------------------------
__global__ void ttrunc_kernel(const float* __restrict__ in,
                              __half* __restrict__ out, int R, int C)
{
    __shared__ float t[32][33];
    int c0 = blockIdx.x * 32, r0 = blockIdx.y * 32;
    int tx = threadIdx.x, ty = threadIdx.y;
#pragma unroll
    for (int i = ty; i < 32; i += 8)
        t[i][tx] = in[(size_t)(r0 + i) * C + c0 + tx];
    __syncthreads();
#pragma unroll
    for (int i = ty; i < 32; i += 8)
        out[(size_t)(c0 + i) * R + r0 + tx] = __float2half_rn(t[tx][i]);
}

// ---------------------------------------------------------------------------
// fp16 MMA GEMM: C[M,N] = A[M,K] @ B[N,K]^T + bias[N]
// CTA tile 128x128 with 4 warps (2M x 2N), warp tile 64x64, 128 threads,
// BK=32, 3 stages (48 KB), 2 CTAs/SM.
// L1 traffic per stage: 16KB STS + 32KB LDSM (A,B each read by 2 warps)
// vs 64KB in the 8-warp 32x64 variant -> MMA-bound.
// MODE 0: fp32 C out.  MODE 1: single fp16 out, cols<DD scaled by SCALE_F.
// ---------------------------------------------------------------------------
#define BK      32
#define STAGES  3
#define TBYTES  8192
#define STG_BYTES (2 * TBYTES)   // A | B
#define NCH     (KK / BK)

__device__ __forceinline__ uint32_t swz(int r, int c) {
    return (uint32_t)(r * 64 + ((c ^ ((r >> 1) & 3)) << 4));
}

template<int MODE>
__global__ __launch_bounds__(128, 2) void gemm_mma_kernel(
    const __half* __restrict__ A, const __half* __restrict__ B,
    const float* __restrict__ bias, float* __restrict__ C,
    __half* __restrict__ CH, int M, int N)
{
    extern __shared__ char smem[];
    const uint32_t sbase = smem_to_u32(smem);

    const int tid = threadIdx.x;
    const int lane = tid & 31;
    const int wid = tid >> 5;        // 0..3
    const int wm = wid & 1;          // 2 warps along M (64 rows each)
    const int wn = wid >> 1;         // 2 warps along N (64 cols each)
    const int m0 = blockIdx.y * 128;
    const int n0 = blockIdx.x * 128;

    // stage loader: 1024 16B-chunks, 8 per thread (128 threads)
    auto load_stage = [&](int kt, int slot) {
        const int k0 = kt * BK;
        const uint32_t st = sbase + slot * STG_BYTES;
#pragma unroll
        for (int i = 0; i < 8; ++i) {
            int idx = tid + i * 128;       // 0..1023
            int tile = idx >> 9;           // 0: A, 1: B
            int rem = idx & 511;
            int r = rem >> 2;
            int c = rem & 3;
            uint32_t dst = st + tile * TBYTES + swz(r, c);
            const __half* gp;
            uint32_t sz = 16;
            if (tile == 0) {
                int m = m0 + r;
                int mc = m < M ? m : 0;
                if (m >= M) sz = 0;
                gp = A + (size_t)mc * KK + k0 + c * 8;
            } else {
                int n = n0 + r;
                gp = B + (size_t)n * KK + k0 + c * 8;
            }
            cp16(dst, gp, sz);
        }
        CP_COMMIT();
    };

    float acc[4][8][4];
#pragma unroll
    for (int t = 0; t < 4; ++t)
#pragma unroll
        for (int j = 0; j < 8; ++j)
#pragma unroll
            for (int v = 0; v < 4; ++v) acc[t][j][v] = 0.f;

    load_stage(0, 0);
    load_stage(1, 1);

    const int arow = wm * 64 + (lane & 15);
    const int acl = lane >> 4;
    const int brow = wn * 64 + (lane & 7) + ((lane >> 4) & 1) * 8;
    const int bcl = (lane >> 3) & 1;

    for (int kt = 0; kt < NCH; ++kt) {
        CP_WAIT(1);
        __syncthreads();
        if (kt + 2 < NCH) load_stage(kt + 2, (kt + 2) % STAGES);

        const uint32_t st = sbase + (kt % STAGES) * STG_BYTES;
#pragma unroll
        for (int ks = 0; ks < 2; ++ks) {
            uint32_t a[4][4], b[4][4];
#pragma unroll
            for (int t = 0; t < 4; ++t)
                ldsm_x4(a[t], st + swz(arow + t * 16, ks * 2 + acl));
#pragma unroll
            for (int jj = 0; jj < 4; ++jj)
                ldsm_x4(b[jj], st + TBYTES + swz(brow + jj * 16, ks * 2 + bcl));
#pragma unroll
            for (int t = 0; t < 4; ++t)
#pragma unroll
                for (int jj = 0; jj < 4; ++jj) {
                    mma_f32(acc[t][jj * 2 + 0], a[t], &b[jj][0]);
                    mma_f32(acc[t][jj * 2 + 1], a[t], &b[jj][2]);
                }
        }
    }

    const int rb = m0 + wm * 64 + (lane >> 2);
    const int cb = n0 + wn * 64 + (lane & 3) * 2;
#pragma unroll
    for (int t = 0; t < 4; ++t) {
        int r0 = rb + t * 16;
#pragma unroll
        for (int j = 0; j < 8; ++j) {
            int col = cb + j * 8;
            float2 b2 = *(const float2*)&bias[col];
            if constexpr (MODE == 0) {
                if (r0 < M) {
                    float2 o = {acc[t][j][0] + b2.x, acc[t][j][1] + b2.y};
                    *(float2*)&C[(size_t)r0 * N + col] = o;
                }
                if (r0 + 8 < M) {
                    float2 o = {acc[t][j][2] + b2.x, acc[t][j][3] + b2.y};
                    *(float2*)&C[(size_t)(r0 + 8) * N + col] = o;
                }
            } else {
                float s = (col < DD) ? SCALE_F : 1.0f;
                if (r0 < M)
                    *(uint32_t*)&CH[(size_t)r0 * N + col] =
                        pack_h2((acc[t][j][0] + b2.x) * s, (acc[t][j][1] + b2.y) * s);
                if (r0 + 8 < M)
                    *(uint32_t*)&CH[(size_t)(r0 + 8) * N + col] =
                        pack_h2((acc[t][j][2] + b2.x) * s, (acc[t][j][3] + b2.y) * s);
            }
        }
    }
}

// ---------------------------------------------------------------------------
// Tensor-core flash attention, plain fp16 (unchanged from R12).
// ---------------------------------------------------------------------------
#define SM_Q    0
#define SM_KV   24576            // buf stride 24576: K@0, V@12288
#define SM_P    73728
#define SM_STAT 90112
#define SM_ATT_TOTAL 92160

__device__ __forceinline__ uint32_t swzQ(int r, int c) {
    return (uint32_t)(r * 192 + ((c ^ ((r >> 1) & 3)) << 4));
}
__device__ __forceinline__ uint32_t swzP(int r, int c) {
    return (uint32_t)(r * 128 + ((c ^ (r & 7)) << 4));
}

__global__ __launch_bounds__(256, 2) void attn_tc_kernel(
    const __half* __restrict__ qkv, __half* __restrict__ att)
{
    extern __shared__ char smem[];
    const uint32_t sb = smem_to_u32(smem);
    const int tid = threadIdx.x;
    const int lane = tid & 31;
    const int wid = tid >> 5;
    const int wm = wid & 3;
    const int wn = wid >> 2;
    const int b = blockIdx.z;
    const int h = blockIdx.y;
    const int q0 = blockIdx.x * 128;

    float* sMax = (float*)(smem + SM_STAT);
    float* sSum = (float*)(smem + SM_STAT + 1024);

    const size_t rowbase = (size_t)b * SS * N1 + (size_t)h * HD;

    {
        int r = tid >> 1;
        int cbase = (tid & 1) * 6;
        int s = q0 + r;
        int sc_ = s < SS ? s : SS - 1;
        const __half* src = qkv + rowbase + (size_t)sc_ * N1;
#pragma unroll
        for (int cc = 0; cc < 6; ++cc) {
            int c = cbase + cc;
            int ca = c < 11 ? c : 10;
            uint32_t sz = (c < 11 && s < SS) ? 16 : 0;
            cp16(sb + SM_Q + swzQ(r, c), src + ca * 8, sz);
        }
    }

    auto load_kv = [&](int kt, int buf) {
        int r = tid >> 2;
        int cbase = (tid & 3) * 3;
        int s = kt * 64 + r;
        int sc_ = s < SS ? s : SS - 1;
        const uint32_t kb = sb + SM_KV + buf * 24576;
        const __half* baseK = qkv + rowbase + (size_t)sc_ * N1 + DD;
        const __half* baseV = qkv + rowbase + (size_t)sc_ * N1 + 2 * DD;
#pragma unroll
        for (int cc = 0; cc < 3; ++cc) {
            int c = cbase + cc;
            int ca = c < 11 ? c : 10;
            uint32_t sz = (c < 11 && s < SS) ? 16 : 0;
            cp16(kb + swzQ(r, c), baseK + ca * 8, sz);
            cp16(kb + 12288 + swzQ(r, c), baseV + ca * 8, sz);
        }
    };

    load_kv(0, 0);
    CP_COMMIT();

    float acc[2][6][4];
#pragma unroll
    for (int ti = 0; ti < 2; ++ti)
#pragma unroll
        for (int j = 0; j < 6; ++j)
#pragma unroll
            for (int v = 0; v < 4; ++v) acc[ti][j][v] = 0.f;
    float m_old[2][2] = {{-1e30f, -1e30f}, {-1e30f, -1e30f}};
    float l_run[2][2] = {{0.f, 0.f}, {0.f, 0.f}};

    const int NKT = (SS + 63) / 64;

    for (int kt = 0; kt < NKT; ++kt) {
        CP_WAIT(0);
        __syncthreads();
        if (kt + 1 < NKT) load_kv(kt + 1, (kt + 1) & 1);
        CP_COMMIT();

        const uint32_t kb = sb + SM_KV + (kt & 1) * 24576;

        // ---- QK^T ----
        float sc[2][4][4];
#pragma unroll
        for (int ti = 0; ti < 2; ++ti)
#pragma unroll
            for (int j = 0; j < 4; ++j)
#pragma unroll
                for (int v = 0; v < 4; ++v) sc[ti][j][v] = 0.f;

#pragma unroll
        for (int ks = 0; ks < 6; ++ks) {
            uint32_t a[2][4], bq[4][2];
#pragma unroll
            for (int ti = 0; ti < 2; ++ti) {
                int r = wm * 32 + ti * 16 + (lane & 15);
                int c = ks * 2 + (lane >> 4);
                ldsm_x4(a[ti], sb + SM_Q + swzQ(r, c));
            }
#pragma unroll
            for (int j = 0; j < 4; ++j) {
                int r = wn * 32 + j * 8 + (lane & 7);
                int c = ks * 2 + ((lane >> 3) & 1);
                ldsm_x2(bq[j], kb + swzQ(r, c));
            }
#pragma unroll
            for (int ti = 0; ti < 2; ++ti)
#pragma unroll
                for (int j = 0; j < 4; ++j)
                    mma_f32(sc[ti][j], a[ti], bq[j]);
        }

        // ---- mask ----
#pragma unroll
        for (int j = 0; j < 4; ++j) {
            int c0 = kt * 64 + wn * 32 + j * 8 + (lane & 3) * 2;
            if (c0 >= SS) { sc[0][j][0] = sc[0][j][2] = sc[1][j][0] = sc[1][j][2] = -1e30f; }
            if (c0 + 1 >= SS) { sc[0][j][1] = sc[0][j][3] = sc[1][j][1] = sc[1][j][3] = -1e30f; }
        }

        // ---- row max ----
#pragma unroll
        for (int ti = 0; ti < 2; ++ti)
#pragma unroll
            for (int hh = 0; hh < 2; ++hh) {
                float mt = -1e30f;
#pragma unroll
                for (int j = 0; j < 4; ++j)
                    mt = fmaxf(mt, fmaxf(sc[ti][j][hh * 2], sc[ti][j][hh * 2 + 1]));
                mt = fmaxf(mt, __shfl_xor_sync(0xffffffffu, mt, 1));
                mt = fmaxf(mt, __shfl_xor_sync(0xffffffffu, mt, 2));
                if ((lane & 3) == 0) {
                    int rl = wm * 32 + ti * 16 + hh * 8 + (lane >> 2);
                    sMax[wn * 128 + rl] = mt;
                }
            }
        __syncthreads();

        float mnew[2][2], corr[2][2];
#pragma unroll
        for (int ti = 0; ti < 2; ++ti)
#pragma unroll
            for (int hh = 0; hh < 2; ++hh) {
                int rl = wm * 32 + ti * 16 + hh * 8 + (lane >> 2);
                float m2 = fmaxf(sMax[rl], sMax[128 + rl]);
                float mn = fmaxf(m_old[ti][hh], m2);
                corr[ti][hh] = __expf(m_old[ti][hh] - mn);
                mnew[ti][hh] = mn;
                m_old[ti][hh] = mn;
            }

        // ---- exp, P store, sums ----
        float sum_[2][2] = {{0.f, 0.f}, {0.f, 0.f}};
#pragma unroll
        for (int ti = 0; ti < 2; ++ti) {
            int r0 = wm * 32 + ti * 16 + (lane >> 2);
#pragma unroll
            for (int j = 0; j < 4; ++j) {
                float p0 = __expf(sc[ti][j][0] - mnew[ti][0]);
                float p1 = __expf(sc[ti][j][1] - mnew[ti][0]);
                float p2 = __expf(sc[ti][j][2] - mnew[ti][1]);
                float p3 = __expf(sc[ti][j][3] - mnew[ti][1]);
                sum_[ti][0] += p0 + p1;
                sum_[ti][1] += p2 + p3;
                int colc = wn * 32 + j * 8 + (lane & 3) * 2;
                uint32_t o0 = swzP(r0, colc >> 3) + (colc & 7) * 2;
                uint32_t o1 = swzP(r0 + 8, colc >> 3) + (colc & 7) * 2;
                *(uint32_t*)(smem + SM_P + o0) = pack_h2(p0, p1);
                *(uint32_t*)(smem + SM_P + o1) = pack_h2(p2, p3);
            }
        }
#pragma unroll
        for (int ti = 0; ti < 2; ++ti)
#pragma unroll
            for (int hh = 0; hh < 2; ++hh) {
                float s = sum_[ti][hh];
                s += __shfl_xor_sync(0xffffffffu, s, 1);
                s += __shfl_xor_sync(0xffffffffu, s, 2);
                if ((lane & 3) == 0) {
                    int rl = wm * 32 + ti * 16 + hh * 8 + (lane >> 2);
                    sSum[wn * 128 + rl] = s;
                }
            }
#pragma unroll
        for (int ti = 0; ti < 2; ++ti)
#pragma unroll
            for (int j = 0; j < 6; ++j) {
                acc[ti][j][0] *= corr[ti][0];
                acc[ti][j][1] *= corr[ti][0];
                acc[ti][j][2] *= corr[ti][1];
                acc[ti][j][3] *= corr[ti][1];
            }
        __syncthreads();
#pragma unroll
        for (int ti = 0; ti < 2; ++ti)
#pragma unroll
            for (int hh = 0; hh < 2; ++hh) {
                int rl = wm * 32 + ti * 16 + hh * 8 + (lane >> 2);
                l_run[ti][hh] = l_run[ti][hh] * corr[ti][hh] + sSum[rl] + sSum[128 + rl];
            }

        // ---- P.V ----
#pragma unroll
        for (int ks = 0; ks < 4; ++ks) {
            uint32_t p[2][4], v[6][2];
#pragma unroll
            for (int ti = 0; ti < 2; ++ti) {
                int r = wm * 32 + ti * 16 + (lane & 15);
                int c = ks * 2 + (lane >> 4);
                ldsm_x4(p[ti], sb + SM_P + swzP(r, c));
            }
#pragma unroll
            for (int j = 0; j < 6; ++j) {
                int rk = ks * 16 + (lane & 15);
                int c = wn * 6 + j;
                ldsm_x2t(v[j], kb + 12288 + swzQ(rk, c));
            }
#pragma unroll
            for (int ti = 0; ti < 2; ++ti)
#pragma unroll
                for (int j = 0; j < 6; ++j)
                    mma_f32(acc[ti][j], p[ti], v[j]);
        }
    }

    // ---- epilogue ----
    float inv[2][2];
#pragma unroll
    for (int ti = 0; ti < 2; ++ti)
#pragma unroll
        for (int hh = 0; hh < 2; ++hh)
            inv[ti][hh] = 1.f / l_run[ti][hh];

#pragma unroll
    for (int ti = 0; ti < 2; ++ti)
#pragma unroll
        for (int j = 0; j < 6; ++j) {
            int col = wn * 48 + j * 8 + (lane & 3) * 2;
            if (col >= HD) continue;
#pragma unroll
            for (int hh = 0; hh < 2; ++hh) {
                int s = q0 + wm * 32 + ti * 16 + hh * 8 + (lane >> 2);
                if (s >= SS) continue;
                float o0 = acc[ti][j][hh * 2] * inv[ti][hh];
                float o1 = acc[ti][j][hh * 2 + 1] * inv[ti][hh];
                size_t off = (size_t)(b * SS + s) * KK + (size_t)h * HD + col;
                *(uint32_t*)&att[off] = pack_h2(o0, o1);
            }
        }
}

// ---------------------------------------------------------------------------
extern "C" void kernel_launch(void* const* d_in, const int* in_sizes, int n_in,
                              void* d_out, int out_size)
{
    const float* hs     = (const float*)d_in[0];
    const float* w_qkv  = (const float*)d_in[1];
    const float* b_qkv  = (const float*)d_in[2];
    const float* w_proj = (const float*)d_in[3];
    const float* b_proj = (const float*)d_in[4];
    float* out = (float*)d_out;

    __half *hsp, *qkv, *att, *wq, *wp;
    cudaGetSymbolAddress((void**)&hsp, g_hs);
    cudaGetSymbolAddress((void**)&qkv, g_qkv);
    cudaGetSymbolAddress((void**)&att, g_att);
    cudaGetSymbolAddress((void**)&wq, g_wqkv);
    cudaGetSymbolAddress((void**)&wp, g_wproj);

    const int gemm_smem = STAGES * STG_BYTES;   // 48 KB
    cudaFuncSetAttribute((const void*)gemm_mma_kernel<0>,
                         cudaFuncAttributeMaxDynamicSharedMemorySize, gemm_smem);
    cudaFuncSetAttribute((const void*)gemm_mma_kernel<1>,
                         cudaFuncAttributeMaxDynamicSharedMemorySize, gemm_smem);
    cudaFuncSetAttribute((const void*)attn_tc_kernel,
                         cudaFuncAttributeMaxDynamicSharedMemorySize, SM_ATT_TOTAL);

    // 0a) round hidden_states to fp16
    {
        int n4 = MM * KK / 4;
        round_kernel<<<(n4 + 255) / 256, 256>>>((const float4*)hs, (uint2*)hsp, n4);
    }
    // 0b) transpose+round weights to fp16
    {
        dim3 g(N1 / 32, KK / 32);
        ttrunc_kernel<<<g, dim3(32, 8)>>>(w_qkv, wq, KK, N1);
    }
    {
        dim3 g(DD / 32, KK / 32);
        ttrunc_kernel<<<g, dim3(32, 8)>>>(w_proj, wp, KK, DD);
    }
    // 1) QKV projection -> single fp16 (q pre-scaled)
    {
        dim3 g(N1 / 128, (MM + 127) / 128);
        gemm_mma_kernel<1><<<g, 128, gemm_smem>>>(hsp, wq, b_qkv,
                                                  nullptr, qkv, MM, N1);
    }
    // 2) flash attention (fp16) -> plain fp16
    {
        dim3 g((SS + 127) / 128, HH, BB);
        attn_tc_kernel<<<g, 256, SM_ATT_TOTAL>>>(qkv, att);
    }
    // 3) output projection -> fp32
    {
        dim3 g(DD / 128, (MM + 127) / 128);
        gemm_mma_kernel<0><<<g, 128, gemm_smem>>>(att, wp, b_proj,
                                                  out, nullptr, MM, DD);
    }
}

// round 14
// speedup vs baseline: 1.3711x; 1.3711x over previous
#include <cuda_runtime.h>
#include <cuda_fp16.h>
#include <cstdint>

// Problem constants
#define BB   16
#define SS   577
#define DD   1408
#define HH   16
#define HD   88
#define SCALE_F 0.10660035817780521f  // 1/sqrt(88)

#define MM   (BB * SS)      // 9232
#define N1   (3 * DD)       // 4224
#define KK   DD             // 1408

// ---------------------------------------------------------------------------
// Device-global scratch (all plain fp16)
// ---------------------------------------------------------------------------
__device__ __half g_hs[(size_t)MM * KK];
__device__ __half g_qkv[(size_t)MM * N1];
__device__ __half g_att[(size_t)MM * KK];
__device__ __half g_wqkv[(size_t)N1 * KK];      // transposed [N,K]
__device__ __half g_wproj[(size_t)DD * KK];     // transposed [N,K]

// ---------------------------------------------------------------------------
// PTX helpers (sm_80+ only; harness targets sm_103 w/o 'a' — no tcgen05)
// ---------------------------------------------------------------------------
__device__ __forceinline__ uint32_t smem_to_u32(const void* p) {
    uint32_t a;
    asm("{ .reg .u64 t; cvta.to.shared.u64 t, %1; cvt.u32.u64 %0, t; }"
        : "=r"(a) : "l"(p));
    return a;
}
__device__ __forceinline__ void cp16(uint32_t dst, const void* src, uint32_t sz) {
    asm volatile("cp.async.ca.shared.global [%0], [%1], 16, %2;"
                 :: "r"(dst), "l"(src), "r"(sz) : "memory");
}
#define CP_COMMIT() asm volatile("cp.async.commit_group;" ::: "memory")
#define CP_WAIT(n)  asm volatile("cp.async.wait_group %0;" :: "n"(n) : "memory")

__device__ __forceinline__ void ldsm_x4(uint32_t* r, uint32_t addr) {
    asm volatile("ldmatrix.sync.aligned.m8n8.x4.shared.b16 {%0,%1,%2,%3}, [%4];"
                 : "=r"(r[0]), "=r"(r[1]), "=r"(r[2]), "=r"(r[3]) : "r"(addr));
}
__device__ __forceinline__ void ldsm_x2(uint32_t* r, uint32_t addr) {
    asm volatile("ldmatrix.sync.aligned.m8n8.x2.shared.b16 {%0,%1}, [%2];"
                 : "=r"(r[0]), "=r"(r[1]) : "r"(addr));
}
__device__ __forceinline__ void ldsm_x2t(uint32_t* r, uint32_t addr) {
    asm volatile("ldmatrix.sync.aligned.m8n8.x2.trans.shared.b16 {%0,%1}, [%2];"
                 : "=r"(r[0]), "=r"(r[1]) : "r"(addr));
}
__device__ __forceinline__ void mma_f32(float* d, const uint32_t* a, const uint32_t* b) {
    asm volatile("mma.sync.aligned.m16n8k16.row.col.f32.f16.f16.f32 "
                 "{%0,%1,%2,%3}, {%4,%5,%6,%7}, {%8,%9}, {%0,%1,%2,%3};"
                 : "+f"(d[0]), "+f"(d[1]), "+f"(d[2]), "+f"(d[3])
                 : "r"(a[0]), "r"(a[1]), "r"(a[2]), "r"(a[3]), "r"(b[0]), "r"(b[1]));
}
__device__ __forceinline__ uint32_t pack_h2(float a, float b) {
    __half2 h = __floats2half2_rn(a, b);
    return *reinterpret_cast<uint32_t*>(&h);
}

// ---------------------------------------------------------------------------
// Round fp32 -> fp16, same layout.
// ---------------------------------------------------------------------------
__global__ void round_kernel(const float4* __restrict__ in,
                             uint2* __restrict__ out, int n4)
{
    int i = blockIdx.x * blockDim.x + threadIdx.x;
    if (i >= n4) return;
    float4 v = in[i];
    uint2 o;
    o.x = pack_h2(v.x, v.y);
    o.y = pack_h2(v.z, v.w);
    out[i] = o;
}

// ---------------------------------------------------------------------------
// Transpose + round: in fp32 [R, C] -> fp16 [C, R]
// ---------------------------------------------------------------------------
__global__ void ttrunc_kernel(const float* __restrict__ in,
                              __half* __restrict__ out, int R, int C)
{
    __shared__ float t[32][33];
    int c0 = blockIdx.x * 32, r0 = blockIdx.y * 32;
    int tx = threadIdx.x, ty = threadIdx.y;
#pragma unroll
    for (int i = ty; i < 32; i += 8)
        t[i][tx] = in[(size_t)(r0 + i) * C + c0 + tx];
    __syncthreads();
#pragma unroll
    for (int i = ty; i < 32; i += 8)
        out[(size_t)(c0 + i) * R + r0 + tx] = __float2half_rn(t[tx][i]);
}

// ---------------------------------------------------------------------------
// fp16 MMA GEMM: C[M,N] = A[M,K] @ B[N,K]^T + bias[N]
// R12 geometry (best measured): CTA 128x128, warp tile 32x64 (8 warps
// 4M x 2N), 2 CTAs/SM. BK=64 per stage as two 32-wide sub-tiles
// (A0|B0|A1|B1, each 8KB) -> half the barriers of BK=32. 3 stages = 96 KB.
// MODE 0: fp32 C out.  MODE 1: single fp16 out, cols<DD scaled by SCALE_F.
// ---------------------------------------------------------------------------
#define BK      64
#define STAGES  3
#define TBYTES  8192
#define STG_BYTES (4 * TBYTES)   // A0 | B0 | A1 | B1
#define NCH     (KK / BK)        // 22

__device__ __forceinline__ uint32_t swz(int r, int c) {
    return (uint32_t)(r * 64 + ((c ^ ((r >> 1) & 3)) << 4));
}

template<int MODE>
__global__ __launch_bounds__(256, 2) void gemm_mma_kernel(
    const __half* __restrict__ A, const __half* __restrict__ B,
    const float* __restrict__ bias, float* __restrict__ C,
    __half* __restrict__ CH, int M, int N)
{
    extern __shared__ char smem[];
    const uint32_t sbase = smem_to_u32(smem);

    const int tid = threadIdx.x;
    const int lane = tid & 31;
    const int wid = tid >> 5;
    const int wm = wid & 3;
    const int wn = wid >> 2;
    const int m0 = blockIdx.y * 128;
    const int n0 = blockIdx.x * 128;

    // stage loader: 2048 16B-chunks (two 32-wide sub-tiles), 8 per thread
    auto load_stage = [&](int kt, int slot) {
        const uint32_t st = sbase + slot * STG_BYTES;
#pragma unroll
        for (int i = 0; i < 8; ++i) {
            int idx = tid + i * 256;       // 0..2047
            int half = idx >> 10;          // k sub-tile 0/1
            int tile = (idx >> 9) & 1;     // 0: A, 1: B
            int rem = idx & 511;
            int r = rem >> 2;
            int c = rem & 3;
            const int k0 = kt * BK + half * 32;
            uint32_t dst = st + (half * 2 + tile) * TBYTES + swz(r, c);
            const __half* gp;
            uint32_t sz = 16;
            if (tile == 0) {
                int m = m0 + r;
                int mc = m < M ? m : 0;
                if (m >= M) sz = 0;
                gp = A + (size_t)mc * KK + k0 + c * 8;
            } else {
                int n = n0 + r;
                gp = B + (size_t)n * KK + k0 + c * 8;
            }
            cp16(dst, gp, sz);
        }
        CP_COMMIT();
    };

    float acc[2][8][4];
#pragma unroll
    for (int t = 0; t < 2; ++t)
#pragma unroll
        for (int j = 0; j < 8; ++j)
#pragma unroll
            for (int v = 0; v < 4; ++v) acc[t][j][v] = 0.f;

    load_stage(0, 0);
    load_stage(1, 1);

    const int ar[2] = { wm * 32 + (lane & 15), wm * 32 + 16 + (lane & 15) };
    const int acl = (lane >> 4);
    const int br = wn * 64 + (lane & 7) + ((lane >> 4) & 1) * 8;
    const int bcl = (lane >> 3) & 1;

    for (int kt = 0; kt < NCH; ++kt) {
        CP_WAIT(1);
        __syncthreads();
        if (kt + 2 < NCH) load_stage(kt + 2, (kt + 2) % STAGES);

        const uint32_t st = sbase + (kt % STAGES) * STG_BYTES;
#pragma unroll
        for (int half = 0; half < 2; ++half) {
            const uint32_t sa = st + half * 2 * TBYTES;
            const uint32_t sb_ = sa + TBYTES;
#pragma unroll
            for (int ks = 0; ks < 2; ++ks) {
                uint32_t a[2][4], b[4][4];
#pragma unroll
                for (int t = 0; t < 2; ++t)
                    ldsm_x4(a[t], sa + swz(ar[t], ks * 2 + acl));
#pragma unroll
                for (int jj = 0; jj < 4; ++jj)
                    ldsm_x4(b[jj], sb_ + swz(br + jj * 16, ks * 2 + bcl));
#pragma unroll
                for (int t = 0; t < 2; ++t)
#pragma unroll
                    for (int jj = 0; jj < 4; ++jj) {
                        mma_f32(acc[t][jj * 2 + 0], a[t], &b[jj][0]);
                        mma_f32(acc[t][jj * 2 + 1], a[t], &b[jj][2]);
                    }
            }
        }
    }

    const int rb = m0 + wm * 32 + (lane >> 2);
    const int cb = n0 + wn * 64 + (lane & 3) * 2;
#pragma unroll
    for (int t = 0; t < 2; ++t) {
        int r0 = rb + t * 16;
#pragma unroll
        for (int j = 0; j < 8; ++j) {
            int col = cb + j * 8;
            float2 b2 = *(const float2*)&bias[col];
            if constexpr (MODE == 0) {
                if (r0 < M) {
                    float2 o = {acc[t][j][0] + b2.x, acc[t][j][1] + b2.y};
                    *(float2*)&C[(size_t)r0 * N + col] = o;
                }
                if (r0 + 8 < M) {
                    float2 o = {acc[t][j][2] + b2.x, acc[t][j][3] + b2.y};
                    *(float2*)&C[(size_t)(r0 + 8) * N + col] = o;
                }
            } else {
                float s = (col < DD) ? SCALE_F : 1.0f;
                if (r0 < M)
                    *(uint32_t*)&CH[(size_t)r0 * N + col] =
                        pack_h2((acc[t][j][0] + b2.x) * s, (acc[t][j][1] + b2.y) * s);
                if (r0 + 8 < M)
                    *(uint32_t*)&CH[(size_t)(r0 + 8) * N + col] =
                        pack_h2((acc[t][j][2] + b2.x) * s, (acc[t][j][3] + b2.y) * s);
            }
        }
    }
}

// ---------------------------------------------------------------------------
// Tensor-core flash attention, plain fp16 (unchanged from R12).
// ---------------------------------------------------------------------------
#define SM_Q    0
#define SM_KV   24576            // buf stride 24576: K@0, V@12288
#define SM_P    73728
#define SM_STAT 90112
#define SM_ATT_TOTAL 92160

__device__ __forceinline__ uint32_t swzQ(int r, int c) {
    return (uint32_t)(r * 192 + ((c ^ ((r >> 1) & 3)) << 4));
}
__device__ __forceinline__ uint32_t swzP(int r, int c) {
    return (uint32_t)(r * 128 + ((c ^ (r & 7)) << 4));
}

__global__ __launch_bounds__(256, 2) void attn_tc_kernel(
    const __half* __restrict__ qkv, __half* __restrict__ att)
{
    extern __shared__ char smem[];
    const uint32_t sb = smem_to_u32(smem);
    const int tid = threadIdx.x;
    const int lane = tid & 31;
    const int wid = tid >> 5;
    const int wm = wid & 3;
    const int wn = wid >> 2;
    const int b = blockIdx.z;
    const int h = blockIdx.y;
    const int q0 = blockIdx.x * 128;

    float* sMax = (float*)(smem + SM_STAT);
    float* sSum = (float*)(smem + SM_STAT + 1024);

    const size_t rowbase = (size_t)b * SS * N1 + (size_t)h * HD;

    {
        int r = tid >> 1;
        int cbase = (tid & 1) * 6;
        int s = q0 + r;
        int sc_ = s < SS ? s : SS - 1;
        const __half* src = qkv + rowbase + (size_t)sc_ * N1;
#pragma unroll
        for (int cc = 0; cc < 6; ++cc) {
            int c = cbase + cc;
            int ca = c < 11 ? c : 10;
            uint32_t sz = (c < 11 && s < SS) ? 16 : 0;
            cp16(sb + SM_Q + swzQ(r, c), src + ca * 8, sz);
        }
    }

    auto load_kv = [&](int kt, int buf) {
        int r = tid >> 2;
        int cbase = (tid & 3) * 3;
        int s = kt * 64 + r;
        int sc_ = s < SS ? s : SS - 1;
        const uint32_t kb = sb + SM_KV + buf * 24576;
        const __half* baseK = qkv + rowbase + (size_t)sc_ * N1 + DD;
        const __half* baseV = qkv + rowbase + (size_t)sc_ * N1 + 2 * DD;
#pragma unroll
        for (int cc = 0; cc < 3; ++cc) {
            int c = cbase + cc;
            int ca = c < 11 ? c : 10;
            uint32_t sz = (c < 11 && s < SS) ? 16 : 0;
            cp16(kb + swzQ(r, c), baseK + ca * 8, sz);
            cp16(kb + 12288 + swzQ(r, c), baseV + ca * 8, sz);
        }
    };

    load_kv(0, 0);
    CP_COMMIT();

    float acc[2][6][4];
#pragma unroll
    for (int ti = 0; ti < 2; ++ti)
#pragma unroll
        for (int j = 0; j < 6; ++j)
#pragma unroll
            for (int v = 0; v < 4; ++v) acc[ti][j][v] = 0.f;
    float m_old[2][2] = {{-1e30f, -1e30f}, {-1e30f, -1e30f}};
    float l_run[2][2] = {{0.f, 0.f}, {0.f, 0.f}};

    const int NKT = (SS + 63) / 64;

    for (int kt = 0; kt < NKT; ++kt) {
        CP_WAIT(0);
        __syncthreads();
        if (kt + 1 < NKT) load_kv(kt + 1, (kt + 1) & 1);
        CP_COMMIT();

        const uint32_t kb = sb + SM_KV + (kt & 1) * 24576;

        // ---- QK^T ----
        float sc[2][4][4];
#pragma unroll
        for (int ti = 0; ti < 2; ++ti)
#pragma unroll
            for (int j = 0; j < 4; ++j)
#pragma unroll
                for (int v = 0; v < 4; ++v) sc[ti][j][v] = 0.f;

#pragma unroll
        for (int ks = 0; ks < 6; ++ks) {
            uint32_t a[2][4], bq[4][2];
#pragma unroll
            for (int ti = 0; ti < 2; ++ti) {
                int r = wm * 32 + ti * 16 + (lane & 15);
                int c = ks * 2 + (lane >> 4);
                ldsm_x4(a[ti], sb + SM_Q + swzQ(r, c));
            }
#pragma unroll
            for (int j = 0; j < 4; ++j) {
                int r = wn * 32 + j * 8 + (lane & 7);
                int c = ks * 2 + ((lane >> 3) & 1);
                ldsm_x2(bq[j], kb + swzQ(r, c));
            }
#pragma unroll
            for (int ti = 0; ti < 2; ++ti)
#pragma unroll
                for (int j = 0; j < 4; ++j)
                    mma_f32(sc[ti][j], a[ti], bq[j]);
        }

        // ---- mask ----
#pragma unroll
        for (int j = 0; j < 4; ++j) {
            int c0 = kt * 64 + wn * 32 + j * 8 + (lane & 3) * 2;
            if (c0 >= SS) { sc[0][j][0] = sc[0][j][2] = sc[1][j][0] = sc[1][j][2] = -1e30f; }
            if (c0 + 1 >= SS) { sc[0][j][1] = sc[0][j][3] = sc[1][j][1] = sc[1][j][3] = -1e30f; }
        }

        // ---- row max ----
#pragma unroll
        for (int ti = 0; ti < 2; ++ti)
#pragma unroll
            for (int hh = 0; hh < 2; ++hh) {
                float mt = -1e30f;
#pragma unroll
                for (int j = 0; j < 4; ++j)
                    mt = fmaxf(mt, fmaxf(sc[ti][j][hh * 2], sc[ti][j][hh * 2 + 1]));
                mt = fmaxf(mt, __shfl_xor_sync(0xffffffffu, mt, 1));
                mt = fmaxf(mt, __shfl_xor_sync(0xffffffffu, mt, 2));
                if ((lane & 3) == 0) {
                    int rl = wm * 32 + ti * 16 + hh * 8 + (lane >> 2);
                    sMax[wn * 128 + rl] = mt;
                }
            }
        __syncthreads();

        float mnew[2][2], corr[2][2];
#pragma unroll
        for (int ti = 0; ti < 2; ++ti)
#pragma unroll
            for (int hh = 0; hh < 2; ++hh) {
                int rl = wm * 32 + ti * 16 + hh * 8 + (lane >> 2);
                float m2 = fmaxf(sMax[rl], sMax[128 + rl]);
                float mn = fmaxf(m_old[ti][hh], m2);
                corr[ti][hh] = __expf(m_old[ti][hh] - mn);
                mnew[ti][hh] = mn;
                m_old[ti][hh] = mn;
            }

        // ---- exp, P store, sums ----
        float sum_[2][2] = {{0.f, 0.f}, {0.f, 0.f}};
#pragma unroll
        for (int ti = 0; ti < 2; ++ti) {
            int r0 = wm * 32 + ti * 16 + (lane >> 2);
#pragma unroll
            for (int j = 0; j < 4; ++j) {
                float p0 = __expf(sc[ti][j][0] - mnew[ti][0]);
                float p1 = __expf(sc[ti][j][1] - mnew[ti][0]);
                float p2 = __expf(sc[ti][j][2] - mnew[ti][1]);
                float p3 = __expf(sc[ti][j][3] - mnew[ti][1]);
                sum_[ti][0] += p0 + p1;
                sum_[ti][1] += p2 + p3;
                int colc = wn * 32 + j * 8 + (lane & 3) * 2;
                uint32_t o0 = swzP(r0, colc >> 3) + (colc & 7) * 2;
                uint32_t o1 = swzP(r0 + 8, colc >> 3) + (colc & 7) * 2;
                *(uint32_t*)(smem + SM_P + o0) = pack_h2(p0, p1);
                *(uint32_t*)(smem + SM_P + o1) = pack_h2(p2, p3);
            }
        }
#pragma unroll
        for (int ti = 0; ti < 2; ++ti)
#pragma unroll
            for (int hh = 0; hh < 2; ++hh) {
                float s = sum_[ti][hh];
                s += __shfl_xor_sync(0xffffffffu, s, 1);
                s += __shfl_xor_sync(0xffffffffu, s, 2);
                if ((lane & 3) == 0) {
                    int rl = wm * 32 + ti * 16 + hh * 8 + (lane >> 2);
                    sSum[wn * 128 + rl] = s;
                }
            }
#pragma unroll
        for (int ti = 0; ti < 2; ++ti)
#pragma unroll
            for (int j = 0; j < 6; ++j) {
                acc[ti][j][0] *= corr[ti][0];
                acc[ti][j][1] *= corr[ti][0];
                acc[ti][j][2] *= corr[ti][1];
                acc[ti][j][3] *= corr[ti][1];
            }
        __syncthreads();
#pragma unroll
        for (int ti = 0; ti < 2; ++ti)
#pragma unroll
            for (int hh = 0; hh < 2; ++hh) {
                int rl = wm * 32 + ti * 16 + hh * 8 + (lane >> 2);
                l_run[ti][hh] = l_run[ti][hh] * corr[ti][hh] + sSum[rl] + sSum[128 + rl];
            }

        // ---- P.V ----
#pragma unroll
        for (int ks = 0; ks < 4; ++ks) {
            uint32_t p[2][4], v[6][2];
#pragma unroll
            for (int ti = 0; ti < 2; ++ti) {
                int r = wm * 32 + ti * 16 + (lane & 15);
                int c = ks * 2 + (lane >> 4);
                ldsm_x4(p[ti], sb + SM_P + swzP(r, c));
            }
#pragma unroll
            for (int j = 0; j < 6; ++j) {
                int rk = ks * 16 + (lane & 15);
                int c = wn * 6 + j;
                ldsm_x2t(v[j], kb + 12288 + swzQ(rk, c));
            }
#pragma unroll
            for (int ti = 0; ti < 2; ++ti)
#pragma unroll
                for (int j = 0; j < 6; ++j)
                    mma_f32(acc[ti][j], p[ti], v[j]);
        }
    }

    // ---- epilogue ----
    float inv[2][2];
#pragma unroll
    for (int ti = 0; ti < 2; ++ti)
#pragma unroll
        for (int hh = 0; hh < 2; ++hh)
            inv[ti][hh] = 1.f / l_run[ti][hh];

#pragma unroll
    for (int ti = 0; ti < 2; ++ti)
#pragma unroll
        for (int j = 0; j < 6; ++j) {
            int col = wn * 48 + j * 8 + (lane & 3) * 2;
            if (col >= HD) continue;
#pragma unroll
            for (int hh = 0; hh < 2; ++hh) {
                int s = q0 + wm * 32 + ti * 16 + hh * 8 + (lane >> 2);
                if (s >= SS) continue;
                float o0 = acc[ti][j][hh * 2] * inv[ti][hh];
                float o1 = acc[ti][j][hh * 2 + 1] * inv[ti][hh];
                size_t off = (size_t)(b * SS + s) * KK + (size_t)h * HD + col;
                *(uint32_t*)&att[off] = pack_h2(o0, o1);
            }
        }
}

// ---------------------------------------------------------------------------
extern "C" void kernel_launch(void* const* d_in, const int* in_sizes, int n_in,
                              void* d_out, int out_size)
{
    const float* hs     = (const float*)d_in[0];
    const float* w_qkv  = (const float*)d_in[1];
    const float* b_qkv  = (const float*)d_in[2];
    const float* w_proj = (const float*)d_in[3];
    const float* b_proj = (const float*)d_in[4];
    float* out = (float*)d_out;

    __half *hsp, *qkv, *att, *wq, *wp;
    cudaGetSymbolAddress((void**)&hsp, g_hs);
    cudaGetSymbolAddress((void**)&qkv, g_qkv);
    cudaGetSymbolAddress((void**)&att, g_att);
    cudaGetSymbolAddress((void**)&wq, g_wqkv);
    cudaGetSymbolAddress((void**)&wp, g_wproj);

    const int gemm_smem = STAGES * STG_BYTES;   // 96 KB
    cudaFuncSetAttribute((const void*)gemm_mma_kernel<0>,
                         cudaFuncAttributeMaxDynamicSharedMemorySize, gemm_smem);
    cudaFuncSetAttribute((const void*)gemm_mma_kernel<1>,
                         cudaFuncAttributeMaxDynamicSharedMemorySize, gemm_smem);
    cudaFuncSetAttribute((const void*)attn_tc_kernel,
                         cudaFuncAttributeMaxDynamicSharedMemorySize, SM_ATT_TOTAL);

    // 0a) round hidden_states to fp16
    {
        int n4 = MM * KK / 4;
        round_kernel<<<(n4 + 255) / 256, 256>>>((const float4*)hs, (uint2*)hsp, n4);
    }
    // 0b) transpose+round weights to fp16
    {
        dim3 g(N1 / 32, KK / 32);
        ttrunc_kernel<<<g, dim3(32, 8)>>>(w_qkv, wq, KK, N1);
    }
    {
        dim3 g(DD / 32, KK / 32);
        ttrunc_kernel<<<g, dim3(32, 8)>>>(w_proj, wp, KK, DD);
    }
    // 1) QKV projection -> single fp16 (q pre-scaled)
    {
        dim3 g(N1 / 128, (MM + 127) / 128);
        gemm_mma_kernel<1><<<g, 256, gemm_smem>>>(hsp, wq, b_qkv,
                                                  nullptr, qkv, MM, N1);
    }
    // 2) flash attention (fp16) -> plain fp16
    {
        dim3 g((SS + 127) / 128, HH, BB);
        attn_tc_kernel<<<g, 256, SM_ATT_TOTAL>>>(qkv, att);
    }
    // 3) output projection -> fp32
    {
        dim3 g(DD / 128, (MM + 127) / 128);
        gemm_mma_kernel<0><<<g, 256, gemm_smem>>>(att, wp, b_proj,
                                                  out, nullptr, MM, DD);
    }
}

// round 15
// speedup vs baseline: 1.4453x; 1.0541x over previous
#include <cuda_runtime.h>
#include <cuda_fp16.h>
#include <cstdint>

// Problem constants
#define BB   16
#define SS   577
#define DD   1408
#define HH   16
#define HD   88
#define SCALE_F 0.10660035817780521f  // 1/sqrt(88)

#define MM   (BB * SS)      // 9232
#define N1   (3 * DD)       // 4224
#define KK   DD             // 1408

// ---------------------------------------------------------------------------
// Device-global scratch (all plain fp16)
// ---------------------------------------------------------------------------
__device__ __half g_hs[(size_t)MM * KK];
__device__ __half g_qkv[(size_t)MM * N1];
__device__ __half g_att[(size_t)MM * KK];
__device__ __half g_wqkv[(size_t)N1 * KK];      // transposed [N,K]
__device__ __half g_wproj[(size_t)DD * KK];     // transposed [N,K]

// ---------------------------------------------------------------------------
// PTX helpers (sm_80+ only; harness targets sm_103 w/o 'a' — no tcgen05)
// ---------------------------------------------------------------------------
__device__ __forceinline__ uint32_t smem_to_u32(const void* p) {
    uint32_t a;
    asm("{ .reg .u64 t; cvta.to.shared.u64 t, %1; cvt.u32.u64 %0, t; }"
        : "=r"(a) : "l"(p));
    return a;
}
// .cg: bypass L1 allocation (L2-only caching) — data has no L1 reuse here.
__device__ __forceinline__ void cp16(uint32_t dst, const void* src, uint32_t sz) {
    asm volatile("cp.async.cg.shared.global [%0], [%1], 16, %2;"
                 :: "r"(dst), "l"(src), "r"(sz) : "memory");
}
#define CP_COMMIT() asm volatile("cp.async.commit_group;" ::: "memory")
#define CP_WAIT(n)  asm volatile("cp.async.wait_group %0;" :: "n"(n) : "memory")

__device__ __forceinline__ void ldsm_x4(uint32_t* r, uint32_t addr) {
    asm volatile("ldmatrix.sync.aligned.m8n8.x4.shared.b16 {%0,%1,%2,%3}, [%4];"
                 : "=r"(r[0]), "=r"(r[1]), "=r"(r[2]), "=r"(r[3]) : "r"(addr));
}
__device__ __forceinline__ void ldsm_x2(uint32_t* r, uint32_t addr) {
    asm volatile("ldmatrix.sync.aligned.m8n8.x2.shared.b16 {%0,%1}, [%2];"
                 : "=r"(r[0]), "=r"(r[1]) : "r"(addr));
}
__device__ __forceinline__ void ldsm_x2t(uint32_t* r, uint32_t addr) {
    asm volatile("ldmatrix.sync.aligned.m8n8.x2.trans.shared.b16 {%0,%1}, [%2];"
                 : "=r"(r[0]), "=r"(r[1]) : "r"(addr));
}
__device__ __forceinline__ void mma_f32(float* d, const uint32_t* a, const uint32_t* b) {
    asm volatile("mma.sync.aligned.m16n8k16.row.col.f32.f16.f16.f32 "
                 "{%0,%1,%2,%3}, {%4,%5,%6,%7}, {%8,%9}, {%0,%1,%2,%3};"
                 : "+f"(d[0]), "+f"(d[1]), "+f"(d[2]), "+f"(d[3])
                 : "r"(a[0]), "r"(a[1]), "r"(a[2]), "r"(a[3]), "r"(b[0]), "r"(b[1]));
}
__device__ __forceinline__ uint32_t pack_h2(float a, float b) {
    __half2 h = __floats2half2_rn(a, b);
    return *reinterpret_cast<uint32_t*>(&h);
}

// ---------------------------------------------------------------------------
// Round fp32 -> fp16, same layout.
// ---------------------------------------------------------------------------
__global__ void round_kernel(const float4* __restrict__ in,
                             uint2* __restrict__ out, int n4)
{
    int i = blockIdx.x * blockDim.x + threadIdx.x;
    if (i >= n4) return;
    float4 v = in[i];
    uint2 o;
    o.x = pack_h2(v.x, v.y);
    o.y = pack_h2(v.z, v.w);
    out[i] = o;
}

// ---------------------------------------------------------------------------
// Transpose + round both weight matrices in one launch (grid.z selects).
// in fp32 [R, C] -> fp16 [C, R].  z=0: w_qkv (C=N1), z=1: w_proj (C=DD).
// ---------------------------------------------------------------------------
__global__ void ttrunc2_kernel(const float* __restrict__ in0, __half* __restrict__ out0,
                               const float* __restrict__ in1, __half* __restrict__ out1,
                               int R, int C0, int C1)
{
    __shared__ float t[32][33];
    const float* in = blockIdx.z ? in1 : in0;
    __half* out = blockIdx.z ? out1 : out0;
    int C = blockIdx.z ? C1 : C0;
    int c0 = blockIdx.x * 32, r0 = blockIdx.y * 32;
    if (c0 >= C) return;
    int tx = threadIdx.x, ty = threadIdx.y;
#pragma unroll
    for (int i = ty; i < 32; i += 8)
        t[i][tx] = in[(size_t)(r0 + i) * C + c0 + tx];
    __syncthreads();
#pragma unroll
    for (int i = ty; i < 32; i += 8)
        out[(size_t)(c0 + i) * R + r0 + tx] = __float2half_rn(t[tx][i]);
}

// ---------------------------------------------------------------------------
// fp16 MMA GEMM: C[M,N] = A[M,K] @ B[N,K]^T + bias[N]
// R14 geometry: CTA 128x128, warp tile 32x64 (8 warps 4M x 2N), 2 CTAs/SM,
// BK=64 per stage as two 32-wide sub-tiles (A0|B0|A1|B1), 3 stages = 96 KB.
// MODE 0: fp32 C out.  MODE 1: single fp16 out, cols<DD scaled by SCALE_F.
// ---------------------------------------------------------------------------
#define BK      64
#define STAGES  3
#define TBYTES  8192
#define STG_BYTES (4 * TBYTES)   // A0 | B0 | A1 | B1
#define NCH     (KK / BK)        // 22

__device__ __forceinline__ uint32_t swz(int r, int c) {
    return (uint32_t)(r * 64 + ((c ^ ((r >> 1) & 3)) << 4));
}

template<int MODE>
__global__ __launch_bounds__(256, 2) void gemm_mma_kernel(
    const __half* __restrict__ A, const __half* __restrict__ B,
    const float* __restrict__ bias, float* __restrict__ C,
    __half* __restrict__ CH, int M, int N)
{
    extern __shared__ char smem[];
    const uint32_t sbase = smem_to_u32(smem);

    const int tid = threadIdx.x;
    const int lane = tid & 31;
    const int wid = tid >> 5;
    const int wm = wid & 3;
    const int wn = wid >> 2;
    const int m0 = blockIdx.y * 128;
    const int n0 = blockIdx.x * 128;

    auto load_stage = [&](int kt, int slot) {
        const uint32_t st = sbase + slot * STG_BYTES;
#pragma unroll
        for (int i = 0; i < 8; ++i) {
            int idx = tid + i * 256;       // 0..2047
            int half = idx >> 10;          // k sub-tile 0/1
            int tile = (idx >> 9) & 1;     // 0: A, 1: B
            int rem = idx & 511;
            int r = rem >> 2;
            int c = rem & 3;
            const int k0 = kt * BK + half * 32;
            uint32_t dst = st + (half * 2 + tile) * TBYTES + swz(r, c);
            const __half* gp;
            uint32_t sz = 16;
            if (tile == 0) {
                int m = m0 + r;
                int mc = m < M ? m : 0;
                if (m >= M) sz = 0;
                gp = A + (size_t)mc * KK + k0 + c * 8;
            } else {
                int n = n0 + r;
                gp = B + (size_t)n * KK + k0 + c * 8;
            }
            cp16(dst, gp, sz);
        }
        CP_COMMIT();
    };

    float acc[2][8][4];
#pragma unroll
    for (int t = 0; t < 2; ++t)
#pragma unroll
        for (int j = 0; j < 8; ++j)
#pragma unroll
            for (int v = 0; v < 4; ++v) acc[t][j][v] = 0.f;

    load_stage(0, 0);
    load_stage(1, 1);

    const int ar[2] = { wm * 32 + (lane & 15), wm * 32 + 16 + (lane & 15) };
    const int acl = (lane >> 4);
    const int br = wn * 64 + (lane & 7) + ((lane >> 4) & 1) * 8;
    const int bcl = (lane >> 3) & 1;

    for (int kt = 0; kt < NCH; ++kt) {
        CP_WAIT(1);
        __syncthreads();
        if (kt + 2 < NCH) load_stage(kt + 2, (kt + 2) % STAGES);

        const uint32_t st = sbase + (kt % STAGES) * STG_BYTES;
#pragma unroll
        for (int half = 0; half < 2; ++half) {
            const uint32_t sa = st + half * 2 * TBYTES;
            const uint32_t sb_ = sa + TBYTES;
#pragma unroll
            for (int ks = 0; ks < 2; ++ks) {
                uint32_t a[2][4], b[4][4];
#pragma unroll
                for (int t = 0; t < 2; ++t)
                    ldsm_x4(a[t], sa + swz(ar[t], ks * 2 + acl));
#pragma unroll
                for (int jj = 0; jj < 4; ++jj)
                    ldsm_x4(b[jj], sb_ + swz(br + jj * 16, ks * 2 + bcl));
#pragma unroll
                for (int t = 0; t < 2; ++t)
#pragma unroll
                    for (int jj = 0; jj < 4; ++jj) {
                        mma_f32(acc[t][jj * 2 + 0], a[t], &b[jj][0]);
                        mma_f32(acc[t][jj * 2 + 1], a[t], &b[jj][2]);
                    }
            }
        }
    }

    const int rb = m0 + wm * 32 + (lane >> 2);
    const int cb = n0 + wn * 64 + (lane & 3) * 2;
#pragma unroll
    for (int t = 0; t < 2; ++t) {
        int r0 = rb + t * 16;
#pragma unroll
        for (int j = 0; j < 8; ++j) {
            int col = cb + j * 8;
            float2 b2 = *(const float2*)&bias[col];
            if constexpr (MODE == 0) {
                if (r0 < M) {
                    float2 o = {acc[t][j][0] + b2.x, acc[t][j][1] + b2.y};
                    *(float2*)&C[(size_t)r0 * N + col] = o;
                }
                if (r0 + 8 < M) {
                    float2 o = {acc[t][j][2] + b2.x, acc[t][j][3] + b2.y};
                    *(float2*)&C[(size_t)(r0 + 8) * N + col] = o;
                }
            } else {
                float s = (col < DD) ? SCALE_F : 1.0f;
                if (r0 < M)
                    *(uint32_t*)&CH[(size_t)r0 * N + col] =
                        pack_h2((acc[t][j][0] + b2.x) * s, (acc[t][j][1] + b2.y) * s);
                if (r0 + 8 < M)
                    *(uint32_t*)&CH[(size_t)(r0 + 8) * N + col] =
                        pack_h2((acc[t][j][2] + b2.x) * s, (acc[t][j][3] + b2.y) * s);
            }
        }
    }
}

// ---------------------------------------------------------------------------
// Tensor-core flash attention, plain fp16 (unchanged from R12/R14).
// ---------------------------------------------------------------------------
#define SM_Q    0
#define SM_KV   24576            // buf stride 24576: K@0, V@12288
#define SM_P    73728
#define SM_STAT 90112
#define SM_ATT_TOTAL 92160

__device__ __forceinline__ uint32_t swzQ(int r, int c) {
    return (uint32_t)(r * 192 + ((c ^ ((r >> 1) & 3)) << 4));
}
__device__ __forceinline__ uint32_t swzP(int r, int c) {
    return (uint32_t)(r * 128 + ((c ^ (r & 7)) << 4));
}

__global__ __launch_bounds__(256, 2) void attn_tc_kernel(
    const __half* __restrict__ qkv, __half* __restrict__ att)
{
    extern __shared__ char smem[];
    const uint32_t sb = smem_to_u32(smem);
    const int tid = threadIdx.x;
    const int lane = tid & 31;
    const int wid = tid >> 5;
    const int wm = wid & 3;
    const int wn = wid >> 2;
    const int b = blockIdx.z;
    const int h = blockIdx.y;
    const int q0 = blockIdx.x * 128;

    float* sMax = (float*)(smem + SM_STAT);
    float* sSum = (float*)(smem + SM_STAT + 1024);

    const size_t rowbase = (size_t)b * SS * N1 + (size_t)h * HD;

    {
        int r = tid >> 1;
        int cbase = (tid & 1) * 6;
        int s = q0 + r;
        int sc_ = s < SS ? s : SS - 1;
        const __half* src = qkv + rowbase + (size_t)sc_ * N1;
#pragma unroll
        for (int cc = 0; cc < 6; ++cc) {
            int c = cbase + cc;
            int ca = c < 11 ? c : 10;
            uint32_t sz = (c < 11 && s < SS) ? 16 : 0;
            cp16(sb + SM_Q + swzQ(r, c), src + ca * 8, sz);
        }
    }

    auto load_kv = [&](int kt, int buf) {
        int r = tid >> 2;
        int cbase = (tid & 3) * 3;
        int s = kt * 64 + r;
        int sc_ = s < SS ? s : SS - 1;
        const uint32_t kb = sb + SM_KV + buf * 24576;
        const __half* baseK = qkv + rowbase + (size_t)sc_ * N1 + DD;
        const __half* baseV = qkv + rowbase + (size_t)sc_ * N1 + 2 * DD;
#pragma unroll
        for (int cc = 0; cc < 3; ++cc) {
            int c = cbase + cc;
            int ca = c < 11 ? c : 10;
            uint32_t sz = (c < 11 && s < SS) ? 16 : 0;
            cp16(kb + swzQ(r, c), baseK + ca * 8, sz);
            cp16(kb + 12288 + swzQ(r, c), baseV + ca * 8, sz);
        }
    };

    load_kv(0, 0);
    CP_COMMIT();

    float acc[2][6][4];
#pragma unroll
    for (int ti = 0; ti < 2; ++ti)
#pragma unroll
        for (int j = 0; j < 6; ++j)
#pragma unroll
            for (int v = 0; v < 4; ++v) acc[ti][j][v] = 0.f;
    float m_old[2][2] = {{-1e30f, -1e30f}, {-1e30f, -1e30f}};
    float l_run[2][2] = {{0.f, 0.f}, {0.f, 0.f}};

    const int NKT = (SS + 63) / 64;

    for (int kt = 0; kt < NKT; ++kt) {
        CP_WAIT(0);
        __syncthreads();
        if (kt + 1 < NKT) load_kv(kt + 1, (kt + 1) & 1);
        CP_COMMIT();

        const uint32_t kb = sb + SM_KV + (kt & 1) * 24576;

        // ---- QK^T ----
        float sc[2][4][4];
#pragma unroll
        for (int ti = 0; ti < 2; ++ti)
#pragma unroll
            for (int j = 0; j < 4; ++j)
#pragma unroll
                for (int v = 0; v < 4; ++v) sc[ti][j][v] = 0.f;

#pragma unroll
        for (int ks = 0; ks < 6; ++ks) {
            uint32_t a[2][4], bq[4][2];
#pragma unroll
            for (int ti = 0; ti < 2; ++ti) {
                int r = wm * 32 + ti * 16 + (lane & 15);
                int c = ks * 2 + (lane >> 4);
                ldsm_x4(a[ti], sb + SM_Q + swzQ(r, c));
            }
#pragma unroll
            for (int j = 0; j < 4; ++j) {
                int r = wn * 32 + j * 8 + (lane & 7);
                int c = ks * 2 + ((lane >> 3) & 1);
                ldsm_x2(bq[j], kb + swzQ(r, c));
            }
#pragma unroll
            for (int ti = 0; ti < 2; ++ti)
#pragma unroll
                for (int j = 0; j < 4; ++j)
                    mma_f32(sc[ti][j], a[ti], bq[j]);
        }

        // ---- mask ----
#pragma unroll
        for (int j = 0; j < 4; ++j) {
            int c0 = kt * 64 + wn * 32 + j * 8 + (lane & 3) * 2;
            if (c0 >= SS) { sc[0][j][0] = sc[0][j][2] = sc[1][j][0] = sc[1][j][2] = -1e30f; }
            if (c0 + 1 >= SS) { sc[0][j][1] = sc[0][j][3] = sc[1][j][1] = sc[1][j][3] = -1e30f; }
        }

        // ---- row max ----
#pragma unroll
        for (int ti = 0; ti < 2; ++ti)
#pragma unroll
            for (int hh = 0; hh < 2; ++hh) {
                float mt = -1e30f;
#pragma unroll
                for (int j = 0; j < 4; ++j)
                    mt = fmaxf(mt, fmaxf(sc[ti][j][hh * 2], sc[ti][j][hh * 2 + 1]));
                mt = fmaxf(mt, __shfl_xor_sync(0xffffffffu, mt, 1));
                mt = fmaxf(mt, __shfl_xor_sync(0xffffffffu, mt, 2));
                if ((lane & 3) == 0) {
                    int rl = wm * 32 + ti * 16 + hh * 8 + (lane >> 2);
                    sMax[wn * 128 + rl] = mt;
                }
            }
        __syncthreads();

        float mnew[2][2], corr[2][2];
#pragma unroll
        for (int ti = 0; ti < 2; ++ti)
#pragma unroll
            for (int hh = 0; hh < 2; ++hh) {
                int rl = wm * 32 + ti * 16 + hh * 8 + (lane >> 2);
                float m2 = fmaxf(sMax[rl], sMax[128 + rl]);
                float mn = fmaxf(m_old[ti][hh], m2);
                corr[ti][hh] = __expf(m_old[ti][hh] - mn);
                mnew[ti][hh] = mn;
                m_old[ti][hh] = mn;
            }

        // ---- exp, P store, sums ----
        float sum_[2][2] = {{0.f, 0.f}, {0.f, 0.f}};
#pragma unroll
        for (int ti = 0; ti < 2; ++ti) {
            int r0 = wm * 32 + ti * 16 + (lane >> 2);
#pragma unroll
            for (int j = 0; j < 4; ++j) {
                float p0 = __expf(sc[ti][j][0] - mnew[ti][0]);
                float p1 = __expf(sc[ti][j][1] - mnew[ti][0]);
                float p2 = __expf(sc[ti][j][2] - mnew[ti][1]);
                float p3 = __expf(sc[ti][j][3] - mnew[ti][1]);
                sum_[ti][0] += p0 + p1;
                sum_[ti][1] += p2 + p3;
                int colc = wn * 32 + j * 8 + (lane & 3) * 2;
                uint32_t o0 = swzP(r0, colc >> 3) + (colc & 7) * 2;
                uint32_t o1 = swzP(r0 + 8, colc >> 3) + (colc & 7) * 2;
                *(uint32_t*)(smem + SM_P + o0) = pack_h2(p0, p1);
                *(uint32_t*)(smem + SM_P + o1) = pack_h2(p2, p3);
            }
        }
#pragma unroll
        for (int ti = 0; ti < 2; ++ti)
#pragma unroll
            for (int hh = 0; hh < 2; ++hh) {
                float s = sum_[ti][hh];
                s += __shfl_xor_sync(0xffffffffu, s, 1);
                s += __shfl_xor_sync(0xffffffffu, s, 2);
                if ((lane & 3) == 0) {
                    int rl = wm * 32 + ti * 16 + hh * 8 + (lane >> 2);
                    sSum[wn * 128 + rl] = s;
                }
            }
#pragma unroll
        for (int ti = 0; ti < 2; ++ti)
#pragma unroll
            for (int j = 0; j < 6; ++j) {
                acc[ti][j][0] *= corr[ti][0];
                acc[ti][j][1] *= corr[ti][0];
                acc[ti][j][2] *= corr[ti][1];
                acc[ti][j][3] *= corr[ti][1];
            }
        __syncthreads();
#pragma unroll
        for (int ti = 0; ti < 2; ++ti)
#pragma unroll
            for (int hh = 0; hh < 2; ++hh) {
                int rl = wm * 32 + ti * 16 + hh * 8 + (lane >> 2);
                l_run[ti][hh] = l_run[ti][hh] * corr[ti][hh] + sSum[rl] + sSum[128 + rl];
            }

        // ---- P.V ----
#pragma unroll
        for (int ks = 0; ks < 4; ++ks) {
            uint32_t p[2][4], v[6][2];
#pragma unroll
            for (int ti = 0; ti < 2; ++ti) {
                int r = wm * 32 + ti * 16 + (lane & 15);
                int c = ks * 2 + (lane >> 4);
                ldsm_x4(p[ti], sb + SM_P + swzP(r, c));
            }
#pragma unroll
            for (int j = 0; j < 6; ++j) {
                int rk = ks * 16 + (lane & 15);
                int c = wn * 6 + j;
                ldsm_x2t(v[j], kb + 12288 + swzQ(rk, c));
            }
#pragma unroll
            for (int ti = 0; ti < 2; ++ti)
#pragma unroll
                for (int j = 0; j < 6; ++j)
                    mma_f32(acc[ti][j], p[ti], v[j]);
        }
    }

    // ---- epilogue ----
    float inv[2][2];
#pragma unroll
    for (int ti = 0; ti < 2; ++ti)
#pragma unroll
        for (int hh = 0; hh < 2; ++hh)
            inv[ti][hh] = 1.f / l_run[ti][hh];

#pragma unroll
    for (int ti = 0; ti < 2; ++ti)
#pragma unroll
        for (int j = 0; j < 6; ++j) {
            int col = wn * 48 + j * 8 + (lane & 3) * 2;
            if (col >= HD) continue;
#pragma unroll
            for (int hh = 0; hh < 2; ++hh) {
                int s = q0 + wm * 32 + ti * 16 + hh * 8 + (lane >> 2);
                if (s >= SS) continue;
                float o0 = acc[ti][j][hh * 2] * inv[ti][hh];
                float o1 = acc[ti][j][hh * 2 + 1] * inv[ti][hh];
                size_t off = (size_t)(b * SS + s) * KK + (size_t)h * HD + col;
                *(uint32_t*)&att[off] = pack_h2(o0, o1);
            }
        }
}

// ---------------------------------------------------------------------------
extern "C" void kernel_launch(void* const* d_in, const int* in_sizes, int n_in,
                              void* d_out, int out_size)
{
    const float* hs     = (const float*)d_in[0];
    const float* w_qkv  = (const float*)d_in[1];
    const float* b_qkv  = (const float*)d_in[2];
    const float* w_proj = (const float*)d_in[3];
    const float* b_proj = (const float*)d_in[4];
    float* out = (float*)d_out;

    __half *hsp, *qkv, *att, *wq, *wp;
    cudaGetSymbolAddress((void**)&hsp, g_hs);
    cudaGetSymbolAddress((void**)&qkv, g_qkv);
    cudaGetSymbolAddress((void**)&att, g_att);
    cudaGetSymbolAddress((void**)&wq, g_wqkv);
    cudaGetSymbolAddress((void**)&wp, g_wproj);

    const int gemm_smem = STAGES * STG_BYTES;   // 96 KB
    cudaFuncSetAttribute((const void*)gemm_mma_kernel<0>,
                         cudaFuncAttributeMaxDynamicSharedMemorySize, gemm_smem);
    cudaFuncSetAttribute((const void*)gemm_mma_kernel<1>,
                         cudaFuncAttributeMaxDynamicSharedMemorySize, gemm_smem);
    cudaFuncSetAttribute((const void*)attn_tc_kernel,
                         cudaFuncAttributeMaxDynamicSharedMemorySize, SM_ATT_TOTAL);

    // 0a) round hidden_states to fp16
    {
        int n4 = MM * KK / 4;
        round_kernel<<<(n4 + 255) / 256, 256>>>((const float4*)hs, (uint2*)hsp, n4);
    }
    // 0b) transpose+round both weights in one launch (z=0: w_qkv, z=1: w_proj)
    {
        dim3 g(N1 / 32, KK / 32, 2);
        ttrunc2_kernel<<<g, dim3(32, 8)>>>(w_qkv, wq, w_proj, wp, KK, N1, DD);
    }
    // 1) QKV projection -> single fp16 (q pre-scaled)
    {
        dim3 g(N1 / 128, (MM + 127) / 128);
        gemm_mma_kernel<1><<<g, 256, gemm_smem>>>(hsp, wq, b_qkv,
                                                  nullptr, qkv, MM, N1);
    }
    // 2) flash attention (fp16) -> plain fp16
    {
        dim3 g((SS + 127) / 128, HH, BB);
        attn_tc_kernel<<<g, 256, SM_ATT_TOTAL>>>(qkv, att);
    }
    // 3) output projection -> fp32
    {
        dim3 g(DD / 128, (MM + 127) / 128);
        gemm_mma_kernel<0><<<g, 256, gemm_smem>>>(att, wp, b_proj,
                                                  out, nullptr, MM, DD);
    }
}

// round 16
// speedup vs baseline: 1.4915x; 1.0319x over previous
#include <cuda_runtime.h>
#include <cuda_fp16.h>
#include <cstdint>

// Problem constants
#define BB   16
#define SS   577
#define DD   1408
#define HH   16
#define HD   88
#define SCALE_F 0.10660035817780521f  // 1/sqrt(88)

#define MM   (BB * SS)      // 9232
#define N1   (3 * DD)       // 4224
#define KK   DD             // 1408

// ---------------------------------------------------------------------------
// Device-global scratch (all plain fp16)
// ---------------------------------------------------------------------------
__device__ __half g_hs[(size_t)MM * KK];
__device__ __half g_qkv[(size_t)MM * N1];
__device__ __half g_att[(size_t)MM * KK];
__device__ __half g_wqkv[(size_t)N1 * KK];      // transposed [N,K]
__device__ __half g_wproj[(size_t)DD * KK];     // transposed [N,K]

// ---------------------------------------------------------------------------
// PTX helpers
// ---------------------------------------------------------------------------
__device__ __forceinline__ uint32_t smem_to_u32(const void* p) {
    uint32_t a;
    asm("{ .reg .u64 t; cvta.to.shared.u64 t, %1; cvt.u32.u64 %0, t; }"
        : "=r"(a) : "l"(p));
    return a;
}
__device__ __forceinline__ void cp16(uint32_t dst, const void* src, uint32_t sz) {
    asm volatile("cp.async.cg.shared.global [%0], [%1], 16, %2;"
                 :: "r"(dst), "l"(src), "r"(sz) : "memory");
}
#define CP_COMMIT() asm volatile("cp.async.commit_group;" ::: "memory")
#define CP_WAIT(n)  asm volatile("cp.async.wait_group %0;" :: "n"(n) : "memory")

__device__ __forceinline__ void ldsm_x4(uint32_t* r, uint32_t addr) {
    asm volatile("ldmatrix.sync.aligned.m8n8.x4.shared.b16 {%0,%1,%2,%3}, [%4];"
                 : "=r"(r[0]), "=r"(r[1]), "=r"(r[2]), "=r"(r[3]) : "r"(addr));
}
__device__ __forceinline__ void ldsm_x4t(uint32_t* r, uint32_t addr) {
    asm volatile("ldmatrix.sync.aligned.m8n8.x4.trans.shared.b16 {%0,%1,%2,%3}, [%4];"
                 : "=r"(r[0]), "=r"(r[1]), "=r"(r[2]), "=r"(r[3]) : "r"(addr));
}
__device__ __forceinline__ void mma_f32(float* d, const uint32_t* a, const uint32_t* b) {
    asm volatile("mma.sync.aligned.m16n8k16.row.col.f32.f16.f16.f32 "
                 "{%0,%1,%2,%3}, {%4,%5,%6,%7}, {%8,%9}, {%0,%1,%2,%3};"
                 : "+f"(d[0]), "+f"(d[1]), "+f"(d[2]), "+f"(d[3])
                 : "r"(a[0]), "r"(a[1]), "r"(a[2]), "r"(a[3]), "r"(b[0]), "r"(b[1]));
}
__device__ __forceinline__ uint32_t pack_h2(float a, float b) {
    __half2 h = __floats2half2_rn(a, b);
    return *reinterpret_cast<uint32_t*>(&h);
}

// ---------------------------------------------------------------------------
// Round fp32 -> fp16, same layout.
// ---------------------------------------------------------------------------
__global__ void round_kernel(const float4* __restrict__ in,
                             uint2* __restrict__ out, int n4)
{
    int i = blockIdx.x * blockDim.x + threadIdx.x;
    if (i >= n4) return;
    float4 v = in[i];
    uint2 o;
    o.x = pack_h2(v.x, v.y);
    o.y = pack_h2(v.z, v.w);
    out[i] = o;
}

// ---------------------------------------------------------------------------
// Transpose + round both weight matrices in one launch (grid.z selects).
// ---------------------------------------------------------------------------
__global__ void ttrunc2_kernel(const float* __restrict__ in0, __half* __restrict__ out0,
                               const float* __restrict__ in1, __half* __restrict__ out1,
                               int R, int C0, int C1)
{
    __shared__ float t[32][33];
    const float* in = blockIdx.z ? in1 : in0;
    __half* out = blockIdx.z ? out1 : out0;
    int C = blockIdx.z ? C1 : C0;
    int c0 = blockIdx.x * 32, r0 = blockIdx.y * 32;
    if (c0 >= C) return;
    int tx = threadIdx.x, ty = threadIdx.y;
#pragma unroll
    for (int i = ty; i < 32; i += 8)
        t[i][tx] = in[(size_t)(r0 + i) * C + c0 + tx];
    __syncthreads();
#pragma unroll
    for (int i = ty; i < 32; i += 8)
        out[(size_t)(c0 + i) * R + r0 + tx] = __float2half_rn(t[tx][i]);
}

// ---------------------------------------------------------------------------
// fp16 MMA GEMM (unchanged from R15 - best measured).
// ---------------------------------------------------------------------------
#define BK      64
#define STAGES  3
#define TBYTES  8192
#define STG_BYTES (4 * TBYTES)
#define NCH     (KK / BK)

__device__ __forceinline__ uint32_t swz(int r, int c) {
    return (uint32_t)(r * 64 + ((c ^ ((r >> 1) & 3)) << 4));
}
__device__ __forceinline__ void ldsm_x2(uint32_t* r, uint32_t addr) {
    asm volatile("ldmatrix.sync.aligned.m8n8.x2.shared.b16 {%0,%1}, [%2];"
                 : "=r"(r[0]), "=r"(r[1]) : "r"(addr));
}

template<int MODE>
__global__ __launch_bounds__(256, 2) void gemm_mma_kernel(
    const __half* __restrict__ A, const __half* __restrict__ B,
    const float* __restrict__ bias, float* __restrict__ C,
    __half* __restrict__ CH, int M, int N)
{
    extern __shared__ char smem[];
    const uint32_t sbase = smem_to_u32(smem);

    const int tid = threadIdx.x;
    const int lane = tid & 31;
    const int wid = tid >> 5;
    const int wm = wid & 3;
    const int wn = wid >> 2;
    const int m0 = blockIdx.y * 128;
    const int n0 = blockIdx.x * 128;

    auto load_stage = [&](int kt, int slot) {
        const uint32_t st = sbase + slot * STG_BYTES;
#pragma unroll
        for (int i = 0; i < 8; ++i) {
            int idx = tid + i * 256;
            int half = idx >> 10;
            int tile = (idx >> 9) & 1;
            int rem = idx & 511;
            int r = rem >> 2;
            int c = rem & 3;
            const int k0 = kt * BK + half * 32;
            uint32_t dst = st + (half * 2 + tile) * TBYTES + swz(r, c);
            const __half* gp;
            uint32_t sz = 16;
            if (tile == 0) {
                int m = m0 + r;
                int mc = m < M ? m : 0;
                if (m >= M) sz = 0;
                gp = A + (size_t)mc * KK + k0 + c * 8;
            } else {
                int n = n0 + r;
                gp = B + (size_t)n * KK + k0 + c * 8;
            }
            cp16(dst, gp, sz);
        }
        CP_COMMIT();
    };

    float acc[2][8][4];
#pragma unroll
    for (int t = 0; t < 2; ++t)
#pragma unroll
        for (int j = 0; j < 8; ++j)
#pragma unroll
            for (int v = 0; v < 4; ++v) acc[t][j][v] = 0.f;

    load_stage(0, 0);
    load_stage(1, 1);

    const int ar[2] = { wm * 32 + (lane & 15), wm * 32 + 16 + (lane & 15) };
    const int acl = (lane >> 4);
    const int br = wn * 64 + (lane & 7) + ((lane >> 4) & 1) * 8;
    const int bcl = (lane >> 3) & 1;

    for (int kt = 0; kt < NCH; ++kt) {
        CP_WAIT(1);
        __syncthreads();
        if (kt + 2 < NCH) load_stage(kt + 2, (kt + 2) % STAGES);

        const uint32_t st = sbase + (kt % STAGES) * STG_BYTES;
#pragma unroll
        for (int half = 0; half < 2; ++half) {
            const uint32_t sa = st + half * 2 * TBYTES;
            const uint32_t sb_ = sa + TBYTES;
#pragma unroll
            for (int ks = 0; ks < 2; ++ks) {
                uint32_t a[2][4], b[4][4];
#pragma unroll
                for (int t = 0; t < 2; ++t)
                    ldsm_x4(a[t], sa + swz(ar[t], ks * 2 + acl));
#pragma unroll
                for (int jj = 0; jj < 4; ++jj)
                    ldsm_x4(b[jj], sb_ + swz(br + jj * 16, ks * 2 + bcl));
#pragma unroll
                for (int t = 0; t < 2; ++t)
#pragma unroll
                    for (int jj = 0; jj < 4; ++jj) {
                        mma_f32(acc[t][jj * 2 + 0], a[t], &b[jj][0]);
                        mma_f32(acc[t][jj * 2 + 1], a[t], &b[jj][2]);
                    }
            }
        }
    }

    const int rb = m0 + wm * 32 + (lane >> 2);
    const int cb = n0 + wn * 64 + (lane & 3) * 2;
#pragma unroll
    for (int t = 0; t < 2; ++t) {
        int r0 = rb + t * 16;
#pragma unroll
        for (int j = 0; j < 8; ++j) {
            int col = cb + j * 8;
            float2 b2 = *(const float2*)&bias[col];
            if constexpr (MODE == 0) {
                if (r0 < M) {
                    float2 o = {acc[t][j][0] + b2.x, acc[t][j][1] + b2.y};
                    *(float2*)&C[(size_t)r0 * N + col] = o;
                }
                if (r0 + 8 < M) {
                    float2 o = {acc[t][j][2] + b2.x, acc[t][j][3] + b2.y};
                    *(float2*)&C[(size_t)(r0 + 8) * N + col] = o;
                }
            } else {
                float s = (col < DD) ? SCALE_F : 1.0f;
                if (r0 < M)
                    *(uint32_t*)&CH[(size_t)r0 * N + col] =
                        pack_h2((acc[t][j][0] + b2.x) * s, (acc[t][j][1] + b2.y) * s);
                if (r0 + 8 < M)
                    *(uint32_t*)&CH[(size_t)(r0 + 8) * N + col] =
                        pack_h2((acc[t][j][2] + b2.x) * s, (acc[t][j][3] + b2.y) * s);
            }
        }
    }
}

// ---------------------------------------------------------------------------
// FA2-style flash attention: warp = 16 query rows x ALL 64 keys.
// In-warp softmax (shfl only), P kept in registers (QK acc layout == PV A
// operand layout after fp16 pack). 1 barrier per kt. smem 72 KB -> 2 CTAs/SM.
// ---------------------------------------------------------------------------
#define SM_Q    0
#define SM_KV   24576            // buf stride 24576: K@0, V@12288
#define SM_ATT_TOTAL 73728

__device__ __forceinline__ uint32_t swzQ(int r, int c) {
    return (uint32_t)(r * 192 + ((c ^ ((r >> 1) & 3)) << 4));
}

__global__ __launch_bounds__(256, 2) void attn_tc_kernel(
    const __half* __restrict__ qkv, __half* __restrict__ att)
{
    extern __shared__ char smem[];
    const uint32_t sb = smem_to_u32(smem);
    const int tid = threadIdx.x;
    const int lane = tid & 31;
    const int wid = tid >> 5;        // warp owns rows wid*16..wid*16+15
    const int b = blockIdx.z;
    const int h = blockIdx.y;
    const int q0 = blockIdx.x * 128;

    const size_t rowbase = (size_t)b * SS * N1 + (size_t)h * HD;

    // Q: 128 rows x 12 chunks; 2 threads/row, 6 chunks each
    {
        int r = tid >> 1;
        int cbase = (tid & 1) * 6;
        int s = q0 + r;
        int sc_ = s < SS ? s : SS - 1;
        const __half* src = qkv + rowbase + (size_t)sc_ * N1;
#pragma unroll
        for (int cc = 0; cc < 6; ++cc) {
            int c = cbase + cc;
            int ca = c < 11 ? c : 10;
            uint32_t sz = (c < 11 && s < SS) ? 16 : 0;
            cp16(sb + SM_Q + swzQ(r, c), src + ca * 8, sz);
        }
    }

    auto load_kv = [&](int kt, int buf) {
        int r = tid >> 2;
        int cbase = (tid & 3) * 3;
        int s = kt * 64 + r;
        int sc_ = s < SS ? s : SS - 1;
        const uint32_t kb = sb + SM_KV + buf * 24576;
        const __half* baseK = qkv + rowbase + (size_t)sc_ * N1 + DD;
        const __half* baseV = qkv + rowbase + (size_t)sc_ * N1 + 2 * DD;
#pragma unroll
        for (int cc = 0; cc < 3; ++cc) {
            int c = cbase + cc;
            int ca = c < 11 ? c : 10;
            uint32_t sz = (c < 11 && s < SS) ? 16 : 0;
            cp16(kb + swzQ(r, c), baseK + ca * 8, sz);
            cp16(kb + 12288 + swzQ(r, c), baseV + ca * 8, sz);
        }
    };

    load_kv(0, 0);
    CP_COMMIT();

    float acc[12][4];                 // 16 rows x 96 dims per warp
#pragma unroll
    for (int j = 0; j < 12; ++j)
#pragma unroll
        for (int v = 0; v < 4; ++v) acc[j][v] = 0.f;
    float m_old[2] = {-1e30f, -1e30f};
    float l_run[2] = {0.f, 0.f};

    const int NKT = (SS + 63) / 64;   // 10

    for (int kt = 0; kt < NKT; ++kt) {
        CP_WAIT(0);
        __syncthreads();              // all warps done reading other buffer
        if (kt + 1 < NKT) load_kv(kt + 1, (kt + 1) & 1);
        CP_COMMIT();

        const uint32_t kb = sb + SM_KV + (kt & 1) * 24576;

        // ---- QK^T: 16 rows x 64 keys, 8 n8 score tiles ----
        float sc[8][4];
#pragma unroll
        for (int j = 0; j < 8; ++j)
#pragma unroll
            for (int v = 0; v < 4; ++v) sc[j][v] = 0.f;

#pragma unroll
        for (int ks = 0; ks < 6; ++ks) {
            uint32_t a[4], kf[4][4];
            ldsm_x4(a, sb + SM_Q + swzQ(wid * 16 + (lane & 15), ks * 2 + (lane >> 4)));
#pragma unroll
            for (int jj = 0; jj < 4; ++jj)
                ldsm_x4(kf[jj], kb + swzQ(jj * 16 + (lane & 7) + ((lane >> 4) & 1) * 8,
                                          ks * 2 + ((lane >> 3) & 1)));
#pragma unroll
            for (int jj = 0; jj < 4; ++jj) {
                mma_f32(sc[jj * 2 + 0], a, &kf[jj][0]);
                mma_f32(sc[jj * 2 + 1], a, &kf[jj][2]);
            }
        }

        // ---- mask ----
#pragma unroll
        for (int j = 0; j < 8; ++j) {
            int c0 = kt * 64 + j * 8 + (lane & 3) * 2;
            if (c0 >= SS) { sc[j][0] = sc[j][2] = -1e30f; }
            if (c0 + 1 >= SS) { sc[j][1] = sc[j][3] = -1e30f; }
        }

        // ---- in-warp row max (shfl only) ----
        float mt[2] = {-1e30f, -1e30f};
#pragma unroll
        for (int j = 0; j < 8; ++j) {
            mt[0] = fmaxf(mt[0], fmaxf(sc[j][0], sc[j][1]));
            mt[1] = fmaxf(mt[1], fmaxf(sc[j][2], sc[j][3]));
        }
#pragma unroll
        for (int hh = 0; hh < 2; ++hh) {
            mt[hh] = fmaxf(mt[hh], __shfl_xor_sync(0xffffffffu, mt[hh], 1));
            mt[hh] = fmaxf(mt[hh], __shfl_xor_sync(0xffffffffu, mt[hh], 2));
        }

        float mnew[2], corr[2];
#pragma unroll
        for (int hh = 0; hh < 2; ++hh) {
            mnew[hh] = fmaxf(m_old[hh], mt[hh]);
            corr[hh] = __expf(m_old[hh] - mnew[hh]);
            m_old[hh] = mnew[hh];
        }

        // ---- exp, pack P into registers (PV A-operand layout), sums ----
        uint32_t pP[8][2];
        float sum_[2] = {0.f, 0.f};
#pragma unroll
        for (int j = 0; j < 8; ++j) {
            float p0 = __expf(sc[j][0] - mnew[0]);
            float p1 = __expf(sc[j][1] - mnew[0]);
            float p2 = __expf(sc[j][2] - mnew[1]);
            float p3 = __expf(sc[j][3] - mnew[1]);
            sum_[0] += p0 + p1;
            sum_[1] += p2 + p3;
            pP[j][0] = pack_h2(p0, p1);
            pP[j][1] = pack_h2(p2, p3);
        }
#pragma unroll
        for (int hh = 0; hh < 2; ++hh) {
            sum_[hh] += __shfl_xor_sync(0xffffffffu, sum_[hh], 1);
            sum_[hh] += __shfl_xor_sync(0xffffffffu, sum_[hh], 2);
            l_run[hh] = l_run[hh] * corr[hh] + sum_[hh];
        }

        // rescale accumulator
#pragma unroll
        for (int j = 0; j < 12; ++j) {
            acc[j][0] *= corr[0];
            acc[j][1] *= corr[0];
            acc[j][2] *= corr[1];
            acc[j][3] *= corr[1];
        }

        // ---- P.V: K-dim 64 keys = 4 k16-steps, 12 n8 dim tiles ----
#pragma unroll
        for (int ks = 0; ks < 4; ++ks) {
            uint32_t pa[4] = { pP[ks * 2][0], pP[ks * 2][1],
                               pP[ks * 2 + 1][0], pP[ks * 2 + 1][1] };
            uint32_t vf[6][4];
#pragma unroll
            for (int cp = 0; cp < 6; ++cp)
                ldsm_x4t(vf[cp], kb + 12288 +
                         swzQ(ks * 16 + (lane & 7) + ((lane >> 3) & 1) * 8,
                              cp * 2 + ((lane >> 4) & 1)));
#pragma unroll
            for (int cp = 0; cp < 6; ++cp) {
                mma_f32(acc[cp * 2 + 0], pa, &vf[cp][0]);
                mma_f32(acc[cp * 2 + 1], pa, &vf[cp][2]);
            }
        }
    }

    // ---- epilogue ----
    float inv[2] = { 1.f / l_run[0], 1.f / l_run[1] };
#pragma unroll
    for (int j = 0; j < 12; ++j) {
        int col = j * 8 + (lane & 3) * 2;
        if (col >= HD) continue;
#pragma unroll
        for (int hh = 0; hh < 2; ++hh) {
            int s = q0 + wid * 16 + hh * 8 + (lane >> 2);
            if (s >= SS) continue;
            float o0 = acc[j][hh * 2] * inv[hh];
            float o1 = acc[j][hh * 2 + 1] * inv[hh];
            size_t off = (size_t)(b * SS + s) * KK + (size_t)h * HD + col;
            *(uint32_t*)&att[off] = pack_h2(o0, o1);
        }
    }
}

// ---------------------------------------------------------------------------
extern "C" void kernel_launch(void* const* d_in, const int* in_sizes, int n_in,
                              void* d_out, int out_size)
{
    const float* hs     = (const float*)d_in[0];
    const float* w_qkv  = (const float*)d_in[1];
    const float* b_qkv  = (const float*)d_in[2];
    const float* w_proj = (const float*)d_in[3];
    const float* b_proj = (const float*)d_in[4];
    float* out = (float*)d_out;

    __half *hsp, *qkv, *att, *wq, *wp;
    cudaGetSymbolAddress((void**)&hsp, g_hs);
    cudaGetSymbolAddress((void**)&qkv, g_qkv);
    cudaGetSymbolAddress((void**)&att, g_att);
    cudaGetSymbolAddress((void**)&wq, g_wqkv);
    cudaGetSymbolAddress((void**)&wp, g_wproj);

    const int gemm_smem = STAGES * STG_BYTES;   // 96 KB
    cudaFuncSetAttribute((const void*)gemm_mma_kernel<0>,
                         cudaFuncAttributeMaxDynamicSharedMemorySize, gemm_smem);
    cudaFuncSetAttribute((const void*)gemm_mma_kernel<1>,
                         cudaFuncAttributeMaxDynamicSharedMemorySize, gemm_smem);
    cudaFuncSetAttribute((const void*)attn_tc_kernel,
                         cudaFuncAttributeMaxDynamicSharedMemorySize, SM_ATT_TOTAL);

    // 0a) round hidden_states to fp16
    {
        int n4 = MM * KK / 4;
        round_kernel<<<(n4 + 255) / 256, 256>>>((const float4*)hs, (uint2*)hsp, n4);
    }
    // 0b) transpose+round both weights in one launch
    {
        dim3 g(N1 / 32, KK / 32, 2);
        ttrunc2_kernel<<<g, dim3(32, 8)>>>(w_qkv, wq, w_proj, wp, KK, N1, DD);
    }
    // 1) QKV projection -> single fp16 (q pre-scaled)
    {
        dim3 g(N1 / 128, (MM + 127) / 128);
        gemm_mma_kernel<1><<<g, 256, gemm_smem>>>(hsp, wq, b_qkv,
                                                  nullptr, qkv, MM, N1);
    }
    // 2) FA2-style flash attention -> plain fp16
    {
        dim3 g((SS + 127) / 128, HH, BB);
        attn_tc_kernel<<<g, 256, SM_ATT_TOTAL>>>(qkv, att);
    }
    // 3) output projection -> fp32
    {
        dim3 g(DD / 128, (MM + 127) / 128);
        gemm_mma_kernel<0><<<g, 256, gemm_smem>>>(att, wp, b_proj,
                                                  out, nullptr, MM, DD);
    }
}